// round 16
// baseline (speedup 1.0000x reference)
#include <cuda_runtime.h>
#include <cuda_fp16.h>
#include <stdint.h>

#define BB 256
#define LL 336
#define NIN 8
#define HH 512
#define PL 96
#define NBE 128
#define NBD 128

// chunked h layout: [mh*8+kc] chunks of 8192 halves; within chunk:
// elem(row,klocal) at ((klocal>>3)*128 + row)*8 + (klocal&7)
__device__ __align__(128) __half g_h0[2][BB*HH];
__device__ __align__(128) __half g_h1[2][BB*HH];
__device__ __align__(128) __half g_ctxc[BB*HH];
__device__ float  g_c1f[BB*HH];
__device__ float  g_yprev[BB];
__device__ __align__(128) __half g_enc[(size_t)LL*BB*HH];     // [l][b][n]
__device__ __align__(128) __half g_xp[(size_t)LL*BB*2048];    // [s][cta128][row128][nl8][4]
__device__ unsigned g_grp_enc[2][8*32], g_grp_dec[2][8*32];
__device__ unsigned g_root_enc[2], g_root_dec[2];
__device__ unsigned g_ep_enc[2], g_ep_dec[2];

__device__ __forceinline__ float sigf(float x) { return 1.f / (1.f + __expf(-x)); }

// two-level tree barrier: 8 groups x 8 CTAs, distinct-line arrival counters,
// root counter, monotonic epoch release. Reset by prep each launch.
__device__ __forceinline__ void gridbar_tree(unsigned* grp, unsigned* root,
                                             unsigned* ep, int gid, unsigned& round) {
    round++;
    __syncthreads();
    __threadfence();
    if (threadIdx.x == 0) {
        unsigned o = atomicAdd(&grp[gid * 32], 1u);
        if (o == round * 8u - 1u) {
            unsigned ro = atomicAdd(root, 1u);
            if (ro == round * 8u - 1u) {
                __threadfence();
                *(volatile unsigned*)ep = round;
            }
        }
        while (*(volatile unsigned*)ep < round) { }
        __threadfence();
    }
    __syncthreads();
}

__device__ __forceinline__ uint32_t smem_u32(const void* p) {
    uint32_t a;
    asm("{ .reg .u64 t; cvta.to.shared.u64 t, %1; cvt.u32.u64 %0, t; }" : "=r"(a) : "l"(p));
    return a;
}
__device__ __forceinline__ void mma16(float c[4], const uint32_t a[4], const uint32_t b[2]) {
    asm volatile(
        "mma.sync.aligned.m16n8k16.row.col.f32.f16.f16.f32 "
        "{%0,%1,%2,%3},{%4,%5,%6,%7},{%8,%9},{%0,%1,%2,%3};"
        : "+f"(c[0]), "+f"(c[1]), "+f"(c[2]), "+f"(c[3])
        : "r"(a[0]), "r"(a[1]), "r"(a[2]), "r"(a[3]), "r"(b[0]), "r"(b[1]));
}
#define LDSM4(r0, r1, r2, r3, addr) \
    asm volatile("ldmatrix.sync.aligned.m8n8.x4.shared.b16 {%0,%1,%2,%3},[%4];" \
                 : "=r"(r0), "=r"(r1), "=r"(r2), "=r"(r3) : "r"(addr))

__device__ __forceinline__ void mbar_init(uint32_t mbar, uint32_t cnt) {
    asm volatile("mbarrier.init.shared.b64 [%0], %1;" :: "r"(mbar), "r"(cnt) : "memory");
}
__device__ __forceinline__ void mbar_wait(uint32_t mbar, uint32_t parity) {
    uint32_t done = 0;
    while (!done) {
        asm volatile(
            "{\n\t.reg .pred p;\n\t"
            "mbarrier.try_wait.parity.acquire.cta.shared::cta.b64 p, [%1], %2, 0x989680;\n\t"
            "selp.b32 %0, 1, 0, p;\n\t}"
            : "=r"(done) : "r"(mbar), "r"(parity) : "memory");
    }
}
__device__ __forceinline__ void issue_bulk(uint32_t dst, const void* src, uint32_t bytes,
                                           uint32_t mbar) {
    asm volatile("mbarrier.arrive.expect_tx.shared.b64 _, [%0], %1;"
                 :: "r"(mbar), "r"(bytes) : "memory");
    asm volatile(
        "cp.async.bulk.shared::cluster.global.mbarrier::complete_tx::bytes [%0], [%1], %2, [%3];"
        :: "r"(dst), "l"(src), "r"(bytes), "r"(mbar) : "memory");
}

// ---------------- prep + xp ----------------
__global__ void prep_kernel() {
    int i = blockIdx.x * blockDim.x + threadIdx.x;
    if (i < BB * HH) {
        g_h0[0][i] = __float2half(0.f);
        g_h1[0][i] = __float2half(0.f);
    }
    if (i < 8 * 32) {
        g_grp_enc[0][i] = 0u; g_grp_enc[1][i] = 0u;
        g_grp_dec[0][i] = 0u; g_grp_dec[1][i] = 0u;
    }
    if (i == 0) {
        g_root_enc[0] = 0u; g_root_enc[1] = 0u;
        g_root_dec[0] = 0u; g_root_dec[1] = 0u;
        g_ep_enc[0] = 0u;   g_ep_enc[1] = 0u;
        g_ep_dec[0] = 0u;   g_ep_dec[1] = 0u;
    }
}

__global__ void xp_kernel(const float* __restrict__ x, const float* __restrict__ Wih0,
                          const float* __restrict__ bi0, const float* __restrict__ bh0) {
    int s = blockIdx.x, c = blockIdx.y, tid = threadIdx.x;
    int mh = c & 1, nb = c >> 1;
    __shared__ float xs[128 * 8];
    __shared__ float Wq[8 * 4 * 8];
    __shared__ float bq[32];
    for (int idx = tid; idx < 1024; idx += 256) {
        int bl = idx >> 3, k = idx & 7;
        xs[idx] = x[((size_t)(mh * 128 + bl) * LL + s) * NIN + k];
    }
    if (tid < 256) {
        int nl = tid >> 5, g = (tid >> 3) & 3, k = tid & 7;
        Wq[tid] = Wih0[(g * HH + nb * 8 + nl) * NIN + k];
    }
    if (tid < 32) {
        int nl = tid >> 2, g = tid & 3;
        bq[tid] = bi0[g * HH + nb * 8 + nl] + bh0[g * HH + nb * 8 + nl];
    }
    __syncthreads();
    int row = tid & 127, part = tid >> 7;
    const float* xr = xs + row * 8;
    __half q16[16];
#pragma unroll
    for (int u = 0; u < 4; u++) {
        int nl = part * 4 + u;
#pragma unroll
        for (int g = 0; g < 4; g++) {
            const float* wr = Wq + (nl * 4 + g) * 8;
            float a = bq[nl * 4 + g];
#pragma unroll
            for (int k = 0; k < 8; k++) a += wr[k] * xr[k];
            q16[u * 4 + g] = __float2half(a);
        }
    }
    __half* dst = g_xp + ((size_t)s * 128 + c) * 4096 + row * 32 + part * 16;
    *(uint4*)(dst)     = *(uint4*)(q16);
    *(uint4*)(dst + 8) = *(uint4*)(q16 + 8);
}

// ---------------- ENCODER: unified 128 CTAs, 4-buffer ring, paired-chunk sync ----------------
#define OF_WL1  33280
#define OF_AB   99328
#define OF_XP   164864
#define OF_HT0  173056
#define OF_HT1  175104
#define OF_B1   177152
#define OF_MBAR 177280
#define ENC_SMEM 177408

__global__ void __launch_bounds__(256, 1) enc_persistent(
    const float* __restrict__ Whh0, const float* __restrict__ Wih1,
    const float* __restrict__ Whh1,
    const float* __restrict__ bi1, const float* __restrict__ bh1) {
    extern __shared__ __align__(16) char smc[];
    __half* WL0 = (__half*)smc;
    __half* WL1 = (__half*)(smc + OF_WL1);
    __half* ht0 = (__half*)(smc + OF_HT0);
    __half* ht1 = (__half*)(smc + OF_HT1);
    float*  bq1 = (float*)(smc + OF_B1);
    uint32_t smb = smem_u32(smc);

    int bx = blockIdx.x, tid = threadIdx.x;
    int lane = tid & 31, wid = tid >> 5;
    int wm = wid >> 1, wn = wid & 1;
    int i4 = lane >> 3, r8 = lane & 7;
    int er = lane >> 2, ec = lane & 3;
    int mh = bx & 1, nb = bx >> 1;
    int gid = nb & 7;

    // ---- weights to smem (32 cols, gate-permuted) ----
    for (int idx = tid; idx < 32 * 128; idx += 256) {
        int cc = idx >> 7, k4 = (idx & 127) * 4;
        int gate = (cc & 1) | (((cc >> 3) & 1) << 1);
        int n = nb * 8 + ((cc >> 4) & 1) * 4 + ((cc >> 1) & 3);
        float4 w = *(const float4*)(Whh0 + (size_t)(gate * HH + n) * HH + k4);
        __half* d = WL0 + (size_t)cc * 520 + k4;
        d[0] = __float2half(w.x); d[1] = __float2half(w.y);
        d[2] = __float2half(w.z); d[3] = __float2half(w.w);
    }
    for (int idx = tid; idx < 32 * 256; idx += 256) {
        int cc = idx >> 8, k4 = (idx & 255) * 4;
        int gate = (cc & 1) | (((cc >> 3) & 1) << 1);
        int n = nb * 8 + ((cc >> 4) & 1) * 4 + ((cc >> 1) & 3);
        int row = gate * HH + n;
        const float* srcW = (k4 < HH) ? Wih1 + (size_t)row * HH + k4
                                      : Whh1 + (size_t)row * HH + (k4 - HH);
        float4 w = *(const float4*)srcW;
        __half* d = WL1 + (size_t)cc * 1032 + k4;
        d[0] = __float2half(w.x); d[1] = __float2half(w.y);
        d[2] = __float2half(w.z); d[3] = __float2half(w.w);
    }
    if (tid < 32) {
        int nl = tid >> 2, g = tid & 3;
        int n = nb * 8 + nl;
        bq1[tid] = bi1[g * HH + n] + bh1[g * HH + n];
    }
    if (tid == 0) {
#pragma unroll
        for (int p = 0; p < 4; p++) mbar_init(smb + OF_MBAR + p * 8, 1);
        mbar_init(smb + OF_MBAR + 32, 1);   // xp
    }
    __syncthreads();

    uint32_t albase = ((uint32_t)((i4 >> 1) & 1)) * 2048 +
                      (uint32_t)(wm * 32 + (i4 & 1) * 8 + r8) * 16;
    int bcol = wn * 16 + ((i4 >> 1) & 1) * 8 + r8;
    int bkh = (i4 & 1) * 8;
    uint32_t bo0 = smb + (uint32_t)(bcol * 520 + bkh) * 2;
    uint32_t bo1 = smb + OF_WL1 + (uint32_t)(bcol * 1032 + bkh) * 2;

    float cst0[4], cst1[4];
#pragma unroll
    for (int i = 0; i < 4; i++) { cst0[i] = 0.f; cst1[i] = 0.f; }

    unsigned cF[4] = {0, 0, 0, 0}, cXP = 0;
    unsigned round = 0;
    for (int s = 0; s <= LL; s++) {
        bool doL0 = (s < LL), doL1 = (s >= 1);
        int nch = doL1 ? 16 : 8;
        const __half* p0 = g_h0[s & 1] + (size_t)mh * 8 * 8192;
        const __half* p1 = g_h1[(s + 1) & 1] + (size_t)mh * 8 * 8192;

        if (tid == 0) {
            if (doL0)
                issue_bulk(smb + OF_XP, g_xp + ((size_t)s * 128 + bx) * 4096, 8192,
                           smb + OF_MBAR + 32);
#pragma unroll
            for (int p = 0; p < 4; p++)
                issue_bulk(smb + OF_AB + p * 16384, p0 + (size_t)p * 8192, 16384,
                           smb + OF_MBAR + p * 8);
        }

        float aL0[2][2][4], aL1[2][2][4];
#pragma unroll
        for (int a = 0; a < 2; a++)
#pragma unroll
            for (int b = 0; b < 2; b++)
#pragma unroll
                for (int q = 0; q < 4; q++) { aL0[a][b][q] = 0.f; aL1[a][b][q] = 0.f; }

        for (int kc = 0; kc < nch; kc += 2) {
#pragma unroll
            for (int h = 0; h < 2; h++) {
                int kk = kc + h;
                int p = kk & 3;
                mbar_wait(smb + OF_MBAR + p * 8, cF[p] & 1);
                cF[p]++;
                bool dL0 = doL0 && kk < 8;
                uint32_t ab = smb + OF_AB + p * 16384;
                uint32_t kb = (uint32_t)(kk * 128);
#pragma unroll
                for (int j = 0; j < 4; j++) {
                    uint32_t a[2][4];
                    LDSM4(a[0][0], a[0][1], a[0][2], a[0][3], ab + albase + j * 4096);
                    LDSM4(a[1][0], a[1][1], a[1][2], a[1][3], ab + albase + j * 4096 + 256);
                    if (dL0) {
                        uint32_t b[4];
                        LDSM4(b[0], b[1], b[2], b[3], bo0 + kb + j * 32);
                        mma16(aL0[0][0], a[0], b);     mma16(aL0[0][1], a[0], b + 2);
                        mma16(aL0[1][0], a[1], b);     mma16(aL0[1][1], a[1], b + 2);
                    }
                    if (doL1) {
                        uint32_t b[4];
                        LDSM4(b[0], b[1], b[2], b[3], bo1 + kb + j * 32);
                        mma16(aL1[0][0], a[0], b);     mma16(aL1[0][1], a[0], b + 2);
                        mma16(aL1[1][0], a[1], b);     mma16(aL1[1][1], a[1], b + 2);
                    }
                }
            }
            __syncthreads();   // both buffers of this pair fully consumed
            if (tid == 0) {
#pragma unroll
                for (int h = 0; h < 2; h++) {
                    int nk = kc + h + 4;
                    if (nk < nch) {
                        int p = nk & 3;
                        const __half* sp = (nk < 8) ? p0 + (size_t)nk * 8192
                                                    : p1 + (size_t)(nk - 8) * 8192;
                        issue_bulk(smb + OF_AB + p * 16384, sp, 16384,
                                   smb + OF_MBAR + p * 8);
                    }
                }
            }
        }

        // ---- fused cells ----
        int nl = wn * 4 + ec;
        if (doL0) {
            mbar_wait(smb + OF_MBAR + 32, cXP & 1);
            cXP++;
            const __half* xpb = (const __half*)(smc + OF_XP);
#pragma unroll
            for (int mi = 0; mi < 2; mi++)
#pragma unroll
                for (int rh = 0; rh < 2; rh++) {
                    int row = wm * 32 + mi * 16 + rh * 8 + er;
                    uint2 xu = *(const uint2*)(xpb + row * 32 + nl * 4);
                    const __half* xh = (const __half*)&xu;
                    float g0 = aL0[mi][0][rh * 2]     + __half2float(xh[0]);
                    float g1 = aL0[mi][0][rh * 2 + 1] + __half2float(xh[1]);
                    float g2 = aL0[mi][1][rh * 2]     + __half2float(xh[2]);
                    float g3 = aL0[mi][1][rh * 2 + 1] + __half2float(xh[3]);
                    float ig = sigf(g0), fg = sigf(g1);
                    float gg = tanhf(g2), og = sigf(g3);
                    int ix = mi * 2 + rh;
                    float cv = fg * cst0[ix] + ig * gg;
                    cst0[ix] = cv;
                    ht0[row * 8 + nl] = __float2half(og * tanhf(cv));
                }
        }
        if (doL1) {
            const float* bp = bq1 + nl * 4;
#pragma unroll
            for (int mi = 0; mi < 2; mi++)
#pragma unroll
                for (int rh = 0; rh < 2; rh++) {
                    int row = wm * 32 + mi * 16 + rh * 8 + er;
                    float g0 = aL1[mi][0][rh * 2]     + bp[0];
                    float g1 = aL1[mi][0][rh * 2 + 1] + bp[1];
                    float g2 = aL1[mi][1][rh * 2]     + bp[2];
                    float g3 = aL1[mi][1][rh * 2 + 1] + bp[3];
                    float ig = sigf(g0), fg = sigf(g1);
                    float gg = tanhf(g2), og = sigf(g3);
                    int ix = mi * 2 + rh;
                    float cv = fg * cst1[ix] + ig * gg;
                    cst1[ix] = cv;
                    ht1[row * 8 + nl] = __float2half(og * tanhf(cv));
                    if (s == LL)
                        g_c1f[(size_t)(mh * 128 + row) * HH + nb * 8 + nl] = cv;
                }
        }
        __syncthreads();
        if (doL0 && tid < 128) {
            uint4 v = *(uint4*)(ht0 + tid * 8);
            *(uint4*)(g_h0[(s + 1) & 1] + (size_t)(mh * 8 + (nb >> 3)) * 8192 +
                      (size_t)((nb & 7) * 128 + tid) * 8) = v;
        }
        if (doL1 && tid >= 128) {
            int row = tid - 128;
            uint4 v = *(uint4*)(ht1 + row * 8);
            *(uint4*)(g_h1[s & 1] + (size_t)(mh * 8 + (nb >> 3)) * 8192 +
                      (size_t)((nb & 7) * 128 + row) * 8) = v;
            *(uint4*)(g_enc + (size_t)(s - 1) * BB * HH +
                      (size_t)(mh * 128 + row) * HH + nb * 8) = v;
        }
        if (s < LL)
            gridbar_tree(g_grp_enc[mh], &g_root_enc[mh], &g_ep_enc[mh], gid, round);
    }
}

// ---------------- DECODER ----------------
#define DOF_AB   66048
#define DOF_PA   131584
#define DOF_PMS  164352
#define DOF_BQ   164480
#define DOF_WD0  164608
#define DOF_MBAR 164736
#define DEC_SMEM 164864

template<int NQ, int KPAD>
__device__ __forceinline__ void mma_chunk(uint32_t abuf, uint32_t wsm, int kglob,
                                          float (&acc)[2][NQ*2][4],
                                          uint32_t albase, int bcol, int bkh) {
#pragma unroll
    for (int j = 0; j < 4; j++) {
        uint32_t a[2][4];
#pragma unroll
        for (int mi = 0; mi < 2; mi++)
            LDSM4(a[mi][0], a[mi][1], a[mi][2], a[mi][3],
                  abuf + albase + j * 4096 + mi * 256);
#pragma unroll
        for (int q = 0; q < NQ; q++) {
            uint32_t b[4];
            LDSM4(b[0], b[1], b[2], b[3],
                  wsm + (uint32_t)((bcol + q * 32) * KPAD + kglob + j * 16 + bkh) * 2);
#pragma unroll
            for (int mi = 0; mi < 2; mi++) {
                mma16(acc[mi][q * 2 + 0], a[mi], b);
                mma16(acc[mi][q * 2 + 1], a[mi], b + 2);
            }
        }
    }
}

// one 8-chunk half; paired chunks per sync
__device__ __forceinline__ void dec_half(const __half* base, int kc0, uint32_t smb,
                                         float (&acc)[2][2][4], unsigned (&cF)[4],
                                         uint32_t albase, int bcol, int bkh, int tid) {
    for (int i = 0; i < 8; i += 2) {
#pragma unroll
        for (int h = 0; h < 2; h++) {
            int ii = i + h;
            int p = ii & 3;
            mbar_wait(smb + DOF_MBAR + p * 8, cF[p] & 1);
            cF[p]++;
            mma_chunk<1, 1032>(smb + DOF_AB + p * 16384, smb, (kc0 + ii) * 64, acc,
                               albase, bcol, bkh);
        }
        __syncthreads();
        if (tid == 0) {
#pragma unroll
            for (int h = 0; h < 2; h++) {
                int nk = i + h + 4;
                if (nk < 8) {
                    int p = nk & 3;
                    issue_bulk(smb + DOF_AB + p * 16384, base + (size_t)nk * 8192, 16384,
                               smb + DOF_MBAR + p * 8);
                }
            }
        }
    }
}

// convert 2 uint4 of halves to 16 floats (once)
__device__ __forceinline__ void cvt16(float* f, uint4 v0, uint4 v1) {
    const __half2* pa = (const __half2*)&v0;
    const __half2* pb = (const __half2*)&v1;
#pragma unroll
    for (int i = 0; i < 4; i++) {
        float2 t = __half22float2(pa[i]);
        f[2 * i] = t.x; f[2 * i + 1] = t.y;
        float2 u = __half22float2(pb[i]);
        f[8 + 2 * i] = u.x; f[8 + 2 * i + 1] = u.y;
    }
}

// both batches (b0, b0+64, same mh half) in one interleaved pass
__device__ void attn_two(int ds, int b0, int b1, bool full, const float* __restrict__ Wfc,
                         const float* __restrict__ bfc, float* __restrict__ out,
                         float* pa, float* pms) {
    int tid = threadIdx.x, lane = tid & 31, w = tid >> 5;
    const __half* h1b = g_h1[ds & 1];
    float hr0[16], hr1[16];
    {
        int mhB = b0 >> 7, rowB = b0 & 127;
        uint4 v0 = *(const uint4*)(h1b + (size_t)(mhB * 8 + (lane >> 3)) * 8192 +
                                   (size_t)((lane & 7) * 128 + rowB) * 8);
        uint4 v1 = *(const uint4*)(h1b + (size_t)(mhB * 8 + 4 + (lane >> 3)) * 8192 +
                                   (size_t)((lane & 7) * 128 + rowB) * 8);
        cvt16(hr0, v0, v1);
    }
    {
        int mhB = b1 >> 7, rowB = b1 & 127;
        uint4 v0 = *(const uint4*)(h1b + (size_t)(mhB * 8 + (lane >> 3)) * 8192 +
                                   (size_t)((lane & 7) * 128 + rowB) * 8);
        uint4 v1 = *(const uint4*)(h1b + (size_t)(mhB * 8 + 4 + (lane >> 3)) * 8192 +
                                   (size_t)((lane & 7) * 128 + rowB) * 8);
        cvt16(hr1, v0, v1);
    }
    if (w == 0) {
        float yv = 0.f;
#pragma unroll
        for (int i = 0; i < 8; i++)
            yv += hr0[i] * Wfc[lane * 8 + i] + hr0[8 + i] * Wfc[256 + lane * 8 + i];
#pragma unroll
        for (int off = 16; off; off >>= 1) yv += __shfl_xor_sync(0xffffffffu, yv, off);
        if (lane == 0) {
            float y = yv + bfc[0];
            if (ds > 0) out[b0 * PL + ds - 1] = y;
            g_yprev[b0] = (ds == 0) ? 0.f : y;
        }
    } else if (w == 1) {
        float yv = 0.f;
#pragma unroll
        for (int i = 0; i < 8; i++)
            yv += hr1[i] * Wfc[lane * 8 + i] + hr1[8 + i] * Wfc[256 + lane * 8 + i];
#pragma unroll
        for (int off = 16; off; off >>= 1) yv += __shfl_xor_sync(0xffffffffu, yv, off);
        if (lane == 0) {
            float y = yv + bfc[0];
            if (ds > 0) out[b1 * PL + ds - 1] = y;
            g_yprev[b1] = (ds == 0) ? 0.f : y;
        }
    }
    if (!full) return;

    float M0 = -1e30f, S0 = 0.f, C0[16];
    float M1 = -1e30f, S1 = 0.f, C1[16];
#pragma unroll
    for (int i = 0; i < 16; i++) { C0[i] = 0.f; C1[i] = 0.f; }
#pragma unroll 2
    for (int l = w; l < LL; l += 8) {
        const uint4* e0 = (const uint4*)(g_enc + ((size_t)l * BB + b0) * HH);
        const uint4* e1 = (const uint4*)(g_enc + ((size_t)l * BB + b1) * HH);
        uint4 v00 = e0[lane], v01 = e0[lane + 32];
        uint4 v10 = e1[lane], v11 = e1[lane + 32];
        float f0[16], f1[16];
        cvt16(f0, v00, v01);
        cvt16(f1, v10, v11);
        float s0 = 0.f, s1 = 0.f;
#pragma unroll
        for (int i = 0; i < 16; i++) {
            s0 += f0[i] * hr0[i];
            s1 += f1[i] * hr1[i];
        }
#pragma unroll
        for (int off = 16; off; off >>= 1) {
            s0 += __shfl_xor_sync(0xffffffffu, s0, off);
            s1 += __shfl_xor_sync(0xffffffffu, s1, off);
        }
        float e0s, e1s;
        if (s0 > M0) {
            float r = __expf(M0 - s0);
            S0 *= r;
#pragma unroll
            for (int i = 0; i < 16; i++) C0[i] *= r;
            M0 = s0;
            e0s = 1.f;
        } else {
            e0s = __expf(s0 - M0);
        }
        S0 += e0s;
        if (s1 > M1) {
            float r = __expf(M1 - s1);
            S1 *= r;
#pragma unroll
            for (int i = 0; i < 16; i++) C1[i] *= r;
            M1 = s1;
            e1s = 1.f;
        } else {
            e1s = __expf(s1 - M1);
        }
        S1 += e1s;
#pragma unroll
        for (int i = 0; i < 16; i++) {
            C0[i] += e0s * f0[i];
            C1[i] += e1s * f1[i];
        }
    }
    if (lane == 0) {
        pms[w * 2] = M0;      pms[w * 2 + 1] = S0;
        pms[16 + w * 2] = M1; pms[16 + w * 2 + 1] = S1;
    }
#pragma unroll
    for (int i = 0; i < 8; i++) {
        pa[w * 512 + lane * 8 + i]       = C0[i];
        pa[w * 512 + 256 + lane * 8 + i] = C0[8 + i];
        pa[4096 + w * 512 + lane * 8 + i]       = C1[i];
        pa[4096 + w * 512 + 256 + lane * 8 + i] = C1[8 + i];
    }
    __syncthreads();
#pragma unroll
    for (int bb = 0; bb < 2; bb++) {
        int b = bb ? b1 : b0;
        int mhB = b >> 7, rowB = b & 127;
        const float* pm = pms + bb * 16;
        const float* pp = pa + bb * 4096;
        float Mg = -1e30f;
#pragma unroll
        for (int ww = 0; ww < 8; ww++) Mg = fmaxf(Mg, pm[ww * 2]);
        float Sg = 0.f;
        float scl[8];
#pragma unroll
        for (int ww = 0; ww < 8; ww++) {
            scl[ww] = __expf(pm[ww * 2] - Mg);
            Sg += pm[ww * 2 + 1] * scl[ww];
        }
        float inv = 1.f / Sg;
        for (int h = tid; h < HH; h += 256) {
            float a = 0.f;
#pragma unroll
            for (int ww = 0; ww < 8; ww++) a += pp[ww * 512 + h] * scl[ww];
            g_ctxc[(size_t)(mhB * 8 + (h >> 6)) * 8192 +
                   (size_t)(((h & 63) >> 3) * 128 + rowB) * 8 + (h & 7)] =
                __float2half(a * inv);
        }
    }
    __syncthreads();
}

__global__ void __launch_bounds__(256, 1) dec_persistent(
    const float* __restrict__ Wdi, const float* __restrict__ Wdh,
    const float* __restrict__ bdi, const float* __restrict__ bdh,
    const float* __restrict__ Wfc, const float* __restrict__ bfc,
    float* __restrict__ out) {
    extern __shared__ __align__(16) char smc[];
    __half* Wsm = (__half*)smc;
    float* pa  = (float*)(smc + DOF_PA);
    float* pms = (float*)(smc + DOF_PMS);
    float* bqd = (float*)(smc + DOF_BQ);
    float* wd0 = (float*)(smc + DOF_WD0);
    uint32_t smb = smem_u32(smc);

    int bx = blockIdx.x, tid = threadIdx.x;
    int lane = tid & 31, wid = tid >> 5;
    int wm = wid >> 1, wn = wid & 1;
    int i4 = lane >> 3, r8 = lane & 7;
    int er = lane >> 2, ec = lane & 3;
    int mh = bx & 1;
    int nb8 = (bx >> 1) * 8;
    int gid = (bx >> 1) & 7;
    int ab0 = mh * 128 + (bx >> 1);
    int ab1 = ab0 + 64;

    for (int idx = tid; idx < 32 * 256; idx += 256) {
        int cc = idx >> 8, k4 = (idx & 255) * 4;
        int gate = (cc & 1) | (((cc >> 3) & 1) << 1);
        int n = nb8 + ((cc >> 4) & 1) * 4 + ((cc >> 1) & 3);
        int row = gate * HH + n;
        float w4[4];
        if (k4 < HH) {
            const float* sp = Wdi + (size_t)row * (HH + 1) + 1 + k4;
            w4[0] = sp[0]; w4[1] = sp[1]; w4[2] = sp[2]; w4[3] = sp[3];
        } else {
            float4 wv = *(const float4*)(Wdh + (size_t)row * HH + (k4 - HH));
            w4[0] = wv.x; w4[1] = wv.y; w4[2] = wv.z; w4[3] = wv.w;
        }
        __half* d = Wsm + (size_t)cc * 1032 + k4;
        d[0] = __float2half(w4[0]); d[1] = __float2half(w4[1]);
        d[2] = __float2half(w4[2]); d[3] = __float2half(w4[3]);
    }
    if (tid < 32) {
        int nl = tid >> 2, g = tid & 3;
        int row = g * HH + nb8 + nl;
        bqd[nl * 4 + g] = bdi[row] + bdh[row];
        wd0[nl * 4 + g] = Wdi[(size_t)row * (HH + 1)];
    }
    if (tid == 0) {
#pragma unroll
        for (int p = 0; p < 4; p++) mbar_init(smb + DOF_MBAR + p * 8, 1);
    }
    __syncthreads();

    uint32_t albase = ((uint32_t)((i4 >> 1) & 1)) * 2048 +
                      (uint32_t)(wm * 32 + (i4 & 1) * 8 + r8) * 16;
    int bcol = wn * 16 + ((i4 >> 1) & 1) * 8 + r8;
    int bkh = (i4 & 1) * 8;

    float cst[4];
#pragma unroll
    for (int mi = 0; mi < 2; mi++)
#pragma unroll
        for (int rh = 0; rh < 2; rh++) {
            int b = mh * 128 + wm * 32 + mi * 16 + rh * 8 + er;
            cst[mi * 2 + rh] = g_c1f[(size_t)b * HH + nb8 + wn * 4 + ec];
        }

    unsigned cF[4] = {0, 0, 0, 0};
    unsigned round = 0;
    for (int ds = 0; ds <= PL; ds++) {
        const __half* p0 = g_ctxc + (size_t)mh * 8 * 8192;
        const __half* p1 = g_h1[ds & 1] + (size_t)mh * 8 * 8192;
        if (ds < PL && tid == 0) {
#pragma unroll
            for (int p = 0; p < 4; p++)
                issue_bulk(smb + DOF_AB + p * 16384, p1 + (size_t)p * 8192, 16384,
                           smb + DOF_MBAR + p * 8);
        }
        attn_two(ds, ab0, ab1, ds < PL, Wfc, bfc, out, pa, pms);
        if (ds == PL) break;

        float acc[2][2][4];
#pragma unroll
        for (int a = 0; a < 2; a++)
#pragma unroll
            for (int b = 0; b < 2; b++)
#pragma unroll
                for (int qd = 0; qd < 4; qd++) acc[a][b][qd] = 0.f;

        // Wdh * h1 half (gemm chunks 8..15) — before the ctx barrier
        dec_half(p1, 8, smb, acc, cF, albase, bcol, bkh, tid);
        gridbar_tree(g_grp_dec[mh], &g_root_dec[mh], &g_ep_dec[mh], gid, round);

        if (tid == 0) {
#pragma unroll
            for (int p = 0; p < 4; p++)
                issue_bulk(smb + DOF_AB + p * 16384, p0 + (size_t)p * 8192, 16384,
                           smb + DOF_MBAR + p * 8);
        }
        dec_half(p0, 0, smb, acc, cF, albase, bcol, bkh, tid);

        {
            int nl = wn * 4 + ec;
            int n = nb8 + nl;
            int kc = n >> 6;
            int seg = (n & 63) >> 3;
            __half* hb = g_h1[(ds + 1) & 1];
#pragma unroll
            for (int mi = 0; mi < 2; mi++)
#pragma unroll
                for (int rh = 0; rh < 2; rh++) {
                    int row = wm * 32 + mi * 16 + rh * 8 + er;
                    int b = mh * 128 + row;
                    float y = g_yprev[b];
                    const float* bp = bqd + nl * 4;
                    const float* wp = wd0 + nl * 4;
                    float g0 = acc[mi][0][rh * 2]     + bp[0] + wp[0] * y;
                    float g1 = acc[mi][0][rh * 2 + 1] + bp[1] + wp[1] * y;
                    float g2 = acc[mi][1][rh * 2]     + bp[2] + wp[2] * y;
                    float g3 = acc[mi][1][rh * 2 + 1] + bp[3] + wp[3] * y;
                    float ig = sigf(g0), fg = sigf(g1);
                    float gg = tanhf(g2), og = sigf(g3);
                    float cv = fg * cst[mi * 2 + rh] + ig * gg;
                    cst[mi * 2 + rh] = cv;
                    hb[(size_t)(mh * 8 + kc) * 8192 + (size_t)(seg * 128 + row) * 8 +
                       (n & 7)] = __float2half(og * tanhf(cv));
                }
        }
        gridbar_tree(g_grp_dec[mh], &g_root_dec[mh], &g_ep_dec[mh], gid, round);
    }
}

extern "C" void kernel_launch(void* const* d_in, const int* in_sizes, int n_in,
                              void* d_out, int out_size) {
    const float* x    = (const float*)d_in[0];
    const float* Wih0 = (const float*)d_in[1];
    const float* Whh0 = (const float*)d_in[2];
    const float* bi0  = (const float*)d_in[3];
    const float* bh0  = (const float*)d_in[4];
    const float* Wih1 = (const float*)d_in[5];
    const float* Whh1 = (const float*)d_in[6];
    const float* bi1  = (const float*)d_in[7];
    const float* bh1  = (const float*)d_in[8];
    const float* Wdi  = (const float*)d_in[9];
    const float* Wdh  = (const float*)d_in[10];
    const float* bdi  = (const float*)d_in[11];
    const float* bdh  = (const float*)d_in[12];
    const float* Wfc  = (const float*)d_in[13];
    const float* bfc  = (const float*)d_in[14];
    float* out = (float*)d_out;

    cudaFuncSetAttribute(enc_persistent, cudaFuncAttributeMaxDynamicSharedMemorySize, ENC_SMEM);
    cudaFuncSetAttribute(dec_persistent, cudaFuncAttributeMaxDynamicSharedMemorySize, DEC_SMEM);

    prep_kernel<<<(BB * HH + 255) / 256, 256>>>();
    xp_kernel<<<dim3(LL, 128), 256>>>(x, Wih0, bi0, bh0);
    enc_persistent<<<NBE, 256, ENC_SMEM>>>(Whh0, Wih1, Whh1, bi1, bh1);
    dec_persistent<<<NBD, 256, DEC_SMEM>>>(Wdi, Wdh, bdi, bdh, Wfc, bfc, out);
}

// round 17
// speedup vs baseline: 1.0998x; 1.0998x over previous
#include <cuda_runtime.h>
#include <cuda_fp16.h>
#include <stdint.h>

#define BB 256
#define LL 336
#define NIN 8
#define HH 512
#define PL 96
#define NBE 128
#define NBD 128

// chunked h layout: [mh*8+kc] chunks of 8192 halves; within chunk:
// elem(row,klocal) at ((klocal>>3)*128 + row)*8 + (klocal&7)
__device__ __align__(128) __half g_h0[2][BB*HH];
__device__ __align__(128) __half g_h1[2][BB*HH];
__device__ __align__(128) __half g_ctxc[BB*HH];
__device__ float  g_c1f[BB*HH];
__device__ float  g_yprev[BB];
__device__ __align__(128) __half g_enc[(size_t)LL*BB*HH];     // [l][b][n]
__device__ __align__(128) __half g_xp[(size_t)LL*BB*2048];    // [s][cta128][row128][nl8][4]
__device__ unsigned g_bar_enc2[2], g_bar_dec2[2];

__device__ __forceinline__ float sigf(float x) { return 1.f / (1.f + __expf(-x)); }

__device__ __forceinline__ void gridbar(unsigned* bar, unsigned& round, unsigned nblk) {
    round++;
    __syncthreads();
    __threadfence();
    if (threadIdx.x == 0) {
        unsigned target = round * nblk;
        atomicAdd(bar, 1u);
        while (*(volatile unsigned*)bar < target) { }
        __threadfence();
    }
    __syncthreads();
}

__device__ __forceinline__ uint32_t smem_u32(const void* p) {
    uint32_t a;
    asm("{ .reg .u64 t; cvta.to.shared.u64 t, %1; cvt.u32.u64 %0, t; }" : "=r"(a) : "l"(p));
    return a;
}
__device__ __forceinline__ void mma16(float c[4], const uint32_t a[4], const uint32_t b[2]) {
    asm volatile(
        "mma.sync.aligned.m16n8k16.row.col.f32.f16.f16.f32 "
        "{%0,%1,%2,%3},{%4,%5,%6,%7},{%8,%9},{%0,%1,%2,%3};"
        : "+f"(c[0]), "+f"(c[1]), "+f"(c[2]), "+f"(c[3])
        : "r"(a[0]), "r"(a[1]), "r"(a[2]), "r"(a[3]), "r"(b[0]), "r"(b[1]));
}
#define LDSM4(r0, r1, r2, r3, addr) \
    asm volatile("ldmatrix.sync.aligned.m8n8.x4.shared.b16 {%0,%1,%2,%3},[%4];" \
                 : "=r"(r0), "=r"(r1), "=r"(r2), "=r"(r3) : "r"(addr))

__device__ __forceinline__ void mbar_init(uint32_t mbar, uint32_t cnt) {
    asm volatile("mbarrier.init.shared.b64 [%0], %1;" :: "r"(mbar), "r"(cnt) : "memory");
}
__device__ __forceinline__ void mbar_wait(uint32_t mbar, uint32_t parity) {
    uint32_t done = 0;
    while (!done) {
        asm volatile(
            "{\n\t.reg .pred p;\n\t"
            "mbarrier.try_wait.parity.acquire.cta.shared::cta.b64 p, [%1], %2, 0x989680;\n\t"
            "selp.b32 %0, 1, 0, p;\n\t}"
            : "=r"(done) : "r"(mbar), "r"(parity) : "memory");
    }
}
__device__ __forceinline__ void issue_bulk(uint32_t dst, const void* src, uint32_t bytes,
                                           uint32_t mbar) {
    asm volatile("mbarrier.arrive.expect_tx.shared.b64 _, [%0], %1;"
                 :: "r"(mbar), "r"(bytes) : "memory");
    asm volatile(
        "cp.async.bulk.shared::cluster.global.mbarrier::complete_tx::bytes [%0], [%1], %2, [%3];"
        :: "r"(dst), "l"(src), "r"(bytes), "r"(mbar) : "memory");
}

// ---------------- prep + xp ----------------
__global__ void prep_kernel() {
    int i = blockIdx.x * blockDim.x + threadIdx.x;
    if (i < BB * HH) {
        g_h0[0][i] = __float2half(0.f);
        g_h1[0][i] = __float2half(0.f);
    }
    if (i == 0) {
        g_bar_enc2[0] = 0u; g_bar_enc2[1] = 0u;
        g_bar_dec2[0] = 0u; g_bar_dec2[1] = 0u;
    }
}

__global__ void xp_kernel(const float* __restrict__ x, const float* __restrict__ Wih0,
                          const float* __restrict__ bi0, const float* __restrict__ bh0) {
    int s = blockIdx.x, c = blockIdx.y, tid = threadIdx.x;
    int mh = c & 1, nb = c >> 1;
    __shared__ float xs[128 * 8];
    __shared__ float Wq[8 * 4 * 8];
    __shared__ float bq[32];
    for (int idx = tid; idx < 1024; idx += 256) {
        int bl = idx >> 3, k = idx & 7;
        xs[idx] = x[((size_t)(mh * 128 + bl) * LL + s) * NIN + k];
    }
    if (tid < 256) {
        int nl = tid >> 5, g = (tid >> 3) & 3, k = tid & 7;
        Wq[tid] = Wih0[(g * HH + nb * 8 + nl) * NIN + k];
    }
    if (tid < 32) {
        int nl = tid >> 2, g = tid & 3;
        bq[tid] = bi0[g * HH + nb * 8 + nl] + bh0[g * HH + nb * 8 + nl];
    }
    __syncthreads();
    int row = tid & 127, part = tid >> 7;
    const float* xr = xs + row * 8;
    __half q16[16];
#pragma unroll
    for (int u = 0; u < 4; u++) {
        int nl = part * 4 + u;
#pragma unroll
        for (int g = 0; g < 4; g++) {
            const float* wr = Wq + (nl * 4 + g) * 8;
            float a = bq[nl * 4 + g];
#pragma unroll
            for (int k = 0; k < 8; k++) a += wr[k] * xr[k];
            q16[u * 4 + g] = __float2half(a);
        }
    }
    __half* dst = g_xp + ((size_t)s * 128 + c) * 4096 + row * 32 + part * 16;
    *(uint4*)(dst)     = *(uint4*)(q16);
    *(uint4*)(dst + 8) = *(uint4*)(q16 + 8);
}

// ---------------- ENCODER: unified 128 CTAs, 4-buffer ring, paired-chunk sync ----------------
#define OF_WL1  33280
#define OF_AB   99328
#define OF_XP   164864
#define OF_HT0  173056
#define OF_HT1  175104
#define OF_B1   177152
#define OF_MBAR 177280
#define ENC_SMEM 177408

__global__ void __launch_bounds__(256, 1) enc_persistent(
    const float* __restrict__ Whh0, const float* __restrict__ Wih1,
    const float* __restrict__ Whh1,
    const float* __restrict__ bi1, const float* __restrict__ bh1) {
    extern __shared__ __align__(16) char smc[];
    __half* WL0 = (__half*)smc;
    __half* WL1 = (__half*)(smc + OF_WL1);
    __half* ht0 = (__half*)(smc + OF_HT0);
    __half* ht1 = (__half*)(smc + OF_HT1);
    float*  bq1 = (float*)(smc + OF_B1);
    uint32_t smb = smem_u32(smc);

    int bx = blockIdx.x, tid = threadIdx.x;
    int lane = tid & 31, wid = tid >> 5;
    int wm = wid >> 1, wn = wid & 1;
    int i4 = lane >> 3, r8 = lane & 7;
    int er = lane >> 2, ec = lane & 3;
    int mh = bx & 1, nb = bx >> 1;

    // ---- weights to smem (32 cols, gate-permuted) ----
    for (int idx = tid; idx < 32 * 128; idx += 256) {
        int cc = idx >> 7, k4 = (idx & 127) * 4;
        int gate = (cc & 1) | (((cc >> 3) & 1) << 1);
        int n = nb * 8 + ((cc >> 4) & 1) * 4 + ((cc >> 1) & 3);
        float4 w = *(const float4*)(Whh0 + (size_t)(gate * HH + n) * HH + k4);
        __half* d = WL0 + (size_t)cc * 520 + k4;
        d[0] = __float2half(w.x); d[1] = __float2half(w.y);
        d[2] = __float2half(w.z); d[3] = __float2half(w.w);
    }
    for (int idx = tid; idx < 32 * 256; idx += 256) {
        int cc = idx >> 8, k4 = (idx & 255) * 4;
        int gate = (cc & 1) | (((cc >> 3) & 1) << 1);
        int n = nb * 8 + ((cc >> 4) & 1) * 4 + ((cc >> 1) & 3);
        int row = gate * HH + n;
        const float* srcW = (k4 < HH) ? Wih1 + (size_t)row * HH + k4
                                      : Whh1 + (size_t)row * HH + (k4 - HH);
        float4 w = *(const float4*)srcW;
        __half* d = WL1 + (size_t)cc * 1032 + k4;
        d[0] = __float2half(w.x); d[1] = __float2half(w.y);
        d[2] = __float2half(w.z); d[3] = __float2half(w.w);
    }
    if (tid < 32) {
        int nl = tid >> 2, g = tid & 3;
        int n = nb * 8 + nl;
        bq1[tid] = bi1[g * HH + n] + bh1[g * HH + n];
    }
    if (tid == 0) {
#pragma unroll
        for (int p = 0; p < 4; p++) mbar_init(smb + OF_MBAR + p * 8, 1);
        mbar_init(smb + OF_MBAR + 32, 1);   // xp
    }
    __syncthreads();

    uint32_t albase = ((uint32_t)((i4 >> 1) & 1)) * 2048 +
                      (uint32_t)(wm * 32 + (i4 & 1) * 8 + r8) * 16;
    int bcol = wn * 16 + ((i4 >> 1) & 1) * 8 + r8;
    int bkh = (i4 & 1) * 8;
    uint32_t bo0 = smb + (uint32_t)(bcol * 520 + bkh) * 2;
    uint32_t bo1 = smb + OF_WL1 + (uint32_t)(bcol * 1032 + bkh) * 2;

    float cst0[4], cst1[4];
#pragma unroll
    for (int i = 0; i < 4; i++) { cst0[i] = 0.f; cst1[i] = 0.f; }

    unsigned cF[4] = {0, 0, 0, 0}, cXP = 0;
    unsigned round = 0;
    for (int s = 0; s <= LL; s++) {
        bool doL0 = (s < LL), doL1 = (s >= 1);
        int nch = doL1 ? 16 : 8;
        const __half* p0 = g_h0[s & 1] + (size_t)mh * 8 * 8192;
        const __half* p1 = g_h1[(s + 1) & 1] + (size_t)mh * 8 * 8192;

        if (tid == 0) {
            if (doL0)
                issue_bulk(smb + OF_XP, g_xp + ((size_t)s * 128 + bx) * 4096, 8192,
                           smb + OF_MBAR + 32);
#pragma unroll
            for (int p = 0; p < 4; p++)
                issue_bulk(smb + OF_AB + p * 16384, p0 + (size_t)p * 8192, 16384,
                           smb + OF_MBAR + p * 8);
        }

        float aL0[2][2][4], aL1[2][2][4];
#pragma unroll
        for (int a = 0; a < 2; a++)
#pragma unroll
            for (int b = 0; b < 2; b++)
#pragma unroll
                for (int q = 0; q < 4; q++) { aL0[a][b][q] = 0.f; aL1[a][b][q] = 0.f; }

        for (int kc = 0; kc < nch; kc += 2) {
#pragma unroll
            for (int h = 0; h < 2; h++) {
                int kk = kc + h;
                int p = kk & 3;
                mbar_wait(smb + OF_MBAR + p * 8, cF[p] & 1);
                cF[p]++;
                bool dL0 = doL0 && kk < 8;
                uint32_t ab = smb + OF_AB + p * 16384;
                uint32_t kb = (uint32_t)(kk * 128);
#pragma unroll
                for (int j = 0; j < 4; j++) {
                    uint32_t a[2][4];
                    LDSM4(a[0][0], a[0][1], a[0][2], a[0][3], ab + albase + j * 4096);
                    LDSM4(a[1][0], a[1][1], a[1][2], a[1][3], ab + albase + j * 4096 + 256);
                    if (dL0) {
                        uint32_t b[4];
                        LDSM4(b[0], b[1], b[2], b[3], bo0 + kb + j * 32);
                        mma16(aL0[0][0], a[0], b);     mma16(aL0[0][1], a[0], b + 2);
                        mma16(aL0[1][0], a[1], b);     mma16(aL0[1][1], a[1], b + 2);
                    }
                    if (doL1) {
                        uint32_t b[4];
                        LDSM4(b[0], b[1], b[2], b[3], bo1 + kb + j * 32);
                        mma16(aL1[0][0], a[0], b);     mma16(aL1[0][1], a[0], b + 2);
                        mma16(aL1[1][0], a[1], b);     mma16(aL1[1][1], a[1], b + 2);
                    }
                }
            }
            if (kc + 4 < nch) {   // sync only when a refill follows (WAR protection)
                __syncthreads();
                if (tid == 0) {
#pragma unroll
                    for (int h = 0; h < 2; h++) {
                        int nk = kc + h + 4;
                        if (nk < nch) {
                            int p = nk & 3;
                            const __half* sp = (nk < 8) ? p0 + (size_t)nk * 8192
                                                        : p1 + (size_t)(nk - 8) * 8192;
                            issue_bulk(smb + OF_AB + p * 16384, sp, 16384,
                                       smb + OF_MBAR + p * 8);
                        }
                    }
                }
            }
        }

        // ---- fused cells ----
        int nl = wn * 4 + ec;
        if (doL0) {
            mbar_wait(smb + OF_MBAR + 32, cXP & 1);
            cXP++;
            const __half* xpb = (const __half*)(smc + OF_XP);
#pragma unroll
            for (int mi = 0; mi < 2; mi++)
#pragma unroll
                for (int rh = 0; rh < 2; rh++) {
                    int row = wm * 32 + mi * 16 + rh * 8 + er;
                    uint2 xu = *(const uint2*)(xpb + row * 32 + nl * 4);
                    const __half* xh = (const __half*)&xu;
                    float g0 = aL0[mi][0][rh * 2]     + __half2float(xh[0]);
                    float g1 = aL0[mi][0][rh * 2 + 1] + __half2float(xh[1]);
                    float g2 = aL0[mi][1][rh * 2]     + __half2float(xh[2]);
                    float g3 = aL0[mi][1][rh * 2 + 1] + __half2float(xh[3]);
                    float ig = sigf(g0), fg = sigf(g1);
                    float gg = tanhf(g2), og = sigf(g3);
                    int ix = mi * 2 + rh;
                    float cv = fg * cst0[ix] + ig * gg;
                    cst0[ix] = cv;
                    ht0[row * 8 + nl] = __float2half(og * tanhf(cv));
                }
        }
        if (doL1) {
            const float* bp = bq1 + nl * 4;
#pragma unroll
            for (int mi = 0; mi < 2; mi++)
#pragma unroll
                for (int rh = 0; rh < 2; rh++) {
                    int row = wm * 32 + mi * 16 + rh * 8 + er;
                    float g0 = aL1[mi][0][rh * 2]     + bp[0];
                    float g1 = aL1[mi][0][rh * 2 + 1] + bp[1];
                    float g2 = aL1[mi][1][rh * 2]     + bp[2];
                    float g3 = aL1[mi][1][rh * 2 + 1] + bp[3];
                    float ig = sigf(g0), fg = sigf(g1);
                    float gg = tanhf(g2), og = sigf(g3);
                    int ix = mi * 2 + rh;
                    float cv = fg * cst1[ix] + ig * gg;
                    cst1[ix] = cv;
                    ht1[row * 8 + nl] = __float2half(og * tanhf(cv));
                    if (s == LL)
                        g_c1f[(size_t)(mh * 128 + row) * HH + nb * 8 + nl] = cv;
                }
        }
        __syncthreads();
        if (doL0 && tid < 128) {
            uint4 v = *(uint4*)(ht0 + tid * 8);
            *(uint4*)(g_h0[(s + 1) & 1] + (size_t)(mh * 8 + (nb >> 3)) * 8192 +
                      (size_t)((nb & 7) * 128 + tid) * 8) = v;
        }
        if (doL1 && tid >= 128) {
            int row = tid - 128;
            uint4 v = *(uint4*)(ht1 + row * 8);
            *(uint4*)(g_h1[s & 1] + (size_t)(mh * 8 + (nb >> 3)) * 8192 +
                      (size_t)((nb & 7) * 128 + row) * 8) = v;
            *(uint4*)(g_enc + (size_t)(s - 1) * BB * HH +
                      (size_t)(mh * 128 + row) * HH + nb * 8) = v;
        }
        if (s < LL) gridbar(&g_bar_enc2[mh], round, 64);
    }
}

// ---------------- DECODER ----------------
#define DOF_AB   66048
#define DOF_PA   131584
#define DOF_PMS  164352
#define DOF_BQ   164480
#define DOF_WD0  164608
#define DOF_MBAR 164736
#define DEC_SMEM 164864

template<int NQ, int KPAD>
__device__ __forceinline__ void mma_chunk(uint32_t abuf, uint32_t wsm, int kglob,
                                          float (&acc)[2][NQ*2][4],
                                          uint32_t albase, int bcol, int bkh) {
#pragma unroll
    for (int j = 0; j < 4; j++) {
        uint32_t a[2][4];
#pragma unroll
        for (int mi = 0; mi < 2; mi++)
            LDSM4(a[mi][0], a[mi][1], a[mi][2], a[mi][3],
                  abuf + albase + j * 4096 + mi * 256);
#pragma unroll
        for (int q = 0; q < NQ; q++) {
            uint32_t b[4];
            LDSM4(b[0], b[1], b[2], b[3],
                  wsm + (uint32_t)((bcol + q * 32) * KPAD + kglob + j * 16 + bkh) * 2);
#pragma unroll
            for (int mi = 0; mi < 2; mi++) {
                mma16(acc[mi][q * 2 + 0], a[mi], b);
                mma16(acc[mi][q * 2 + 1], a[mi], b + 2);
            }
        }
    }
}

// one 8-chunk half; paired chunks per sync; sync only before refills
__device__ __forceinline__ void dec_half(const __half* base, int kc0, uint32_t smb,
                                         float (&acc)[2][2][4], unsigned (&cF)[4],
                                         uint32_t albase, int bcol, int bkh, int tid) {
    for (int i = 0; i < 8; i += 2) {
#pragma unroll
        for (int h = 0; h < 2; h++) {
            int ii = i + h;
            int p = ii & 3;
            mbar_wait(smb + DOF_MBAR + p * 8, cF[p] & 1);
            cF[p]++;
            mma_chunk<1, 1032>(smb + DOF_AB + p * 16384, smb, (kc0 + ii) * 64, acc,
                               albase, bcol, bkh);
        }
        if (i + 4 < 8) {
            __syncthreads();
            if (tid == 0) {
#pragma unroll
                for (int h = 0; h < 2; h++) {
                    int nk = i + h + 4;
                    if (nk < 8) {
                        int p = nk & 3;
                        issue_bulk(smb + DOF_AB + p * 16384, base + (size_t)nk * 8192,
                                   16384, smb + DOF_MBAR + p * 8);
                    }
                }
            }
        }
    }
}

// convert 2 uint4 of halves to 16 floats (once)
__device__ __forceinline__ void cvt16(float* f, uint4 v0, uint4 v1) {
    const __half2* pa = (const __half2*)&v0;
    const __half2* pb = (const __half2*)&v1;
#pragma unroll
    for (int i = 0; i < 4; i++) {
        float2 t = __half22float2(pa[i]);
        f[2 * i] = t.x; f[2 * i + 1] = t.y;
        float2 u = __half22float2(pb[i]);
        f[8 + 2 * i] = u.x; f[8 + 2 * i + 1] = u.y;
    }
}

// both batches (b0, b0+64, same mh half) in one interleaved pass
__device__ void attn_two(int ds, int b0, int b1, bool full, const float* __restrict__ Wfc,
                         const float* __restrict__ bfc, float* __restrict__ out,
                         float* pa, float* pms) {
    int tid = threadIdx.x, lane = tid & 31, w = tid >> 5;
    const __half* h1b = g_h1[ds & 1];
    float hr0[16], hr1[16];
    {
        int mhB = b0 >> 7, rowB = b0 & 127;
        uint4 v0 = *(const uint4*)(h1b + (size_t)(mhB * 8 + (lane >> 3)) * 8192 +
                                   (size_t)((lane & 7) * 128 + rowB) * 8);
        uint4 v1 = *(const uint4*)(h1b + (size_t)(mhB * 8 + 4 + (lane >> 3)) * 8192 +
                                   (size_t)((lane & 7) * 128 + rowB) * 8);
        cvt16(hr0, v0, v1);
    }
    {
        int mhB = b1 >> 7, rowB = b1 & 127;
        uint4 v0 = *(const uint4*)(h1b + (size_t)(mhB * 8 + (lane >> 3)) * 8192 +
                                   (size_t)((lane & 7) * 128 + rowB) * 8);
        uint4 v1 = *(const uint4*)(h1b + (size_t)(mhB * 8 + 4 + (lane >> 3)) * 8192 +
                                   (size_t)((lane & 7) * 128 + rowB) * 8);
        cvt16(hr1, v0, v1);
    }
    if (w == 0) {
        float yv = 0.f;
#pragma unroll
        for (int i = 0; i < 8; i++)
            yv += hr0[i] * Wfc[lane * 8 + i] + hr0[8 + i] * Wfc[256 + lane * 8 + i];
#pragma unroll
        for (int off = 16; off; off >>= 1) yv += __shfl_xor_sync(0xffffffffu, yv, off);
        if (lane == 0) {
            float y = yv + bfc[0];
            if (ds > 0) out[b0 * PL + ds - 1] = y;
            g_yprev[b0] = (ds == 0) ? 0.f : y;
        }
    } else if (w == 1) {
        float yv = 0.f;
#pragma unroll
        for (int i = 0; i < 8; i++)
            yv += hr1[i] * Wfc[lane * 8 + i] + hr1[8 + i] * Wfc[256 + lane * 8 + i];
#pragma unroll
        for (int off = 16; off; off >>= 1) yv += __shfl_xor_sync(0xffffffffu, yv, off);
        if (lane == 0) {
            float y = yv + bfc[0];
            if (ds > 0) out[b1 * PL + ds - 1] = y;
            g_yprev[b1] = (ds == 0) ? 0.f : y;
        }
    }
    if (!full) return;

    float M0 = -1e30f, S0 = 0.f, C0[16];
    float M1 = -1e30f, S1 = 0.f, C1[16];
#pragma unroll
    for (int i = 0; i < 16; i++) { C0[i] = 0.f; C1[i] = 0.f; }
#pragma unroll 2
    for (int l = w; l < LL; l += 8) {
        const uint4* e0 = (const uint4*)(g_enc + ((size_t)l * BB + b0) * HH);
        const uint4* e1 = (const uint4*)(g_enc + ((size_t)l * BB + b1) * HH);
        uint4 v00 = e0[lane], v01 = e0[lane + 32];
        uint4 v10 = e1[lane], v11 = e1[lane + 32];
        float f0[16], f1[16];
        cvt16(f0, v00, v01);
        cvt16(f1, v10, v11);
        float s0 = 0.f, s1 = 0.f;
#pragma unroll
        for (int i = 0; i < 16; i++) {
            s0 += f0[i] * hr0[i];
            s1 += f1[i] * hr1[i];
        }
#pragma unroll
        for (int off = 16; off; off >>= 1) {
            s0 += __shfl_xor_sync(0xffffffffu, s0, off);
            s1 += __shfl_xor_sync(0xffffffffu, s1, off);
        }
        float e0s, e1s;
        if (s0 > M0) {
            float r = __expf(M0 - s0);
            S0 *= r;
#pragma unroll
            for (int i = 0; i < 16; i++) C0[i] *= r;
            M0 = s0;
            e0s = 1.f;
        } else {
            e0s = __expf(s0 - M0);
        }
        S0 += e0s;
        if (s1 > M1) {
            float r = __expf(M1 - s1);
            S1 *= r;
#pragma unroll
            for (int i = 0; i < 16; i++) C1[i] *= r;
            M1 = s1;
            e1s = 1.f;
        } else {
            e1s = __expf(s1 - M1);
        }
        S1 += e1s;
#pragma unroll
        for (int i = 0; i < 16; i++) {
            C0[i] += e0s * f0[i];
            C1[i] += e1s * f1[i];
        }
    }
    if (lane == 0) {
        pms[w * 2] = M0;      pms[w * 2 + 1] = S0;
        pms[16 + w * 2] = M1; pms[16 + w * 2 + 1] = S1;
    }
#pragma unroll
    for (int i = 0; i < 8; i++) {
        pa[w * 512 + lane * 8 + i]       = C0[i];
        pa[w * 512 + 256 + lane * 8 + i] = C0[8 + i];
        pa[4096 + w * 512 + lane * 8 + i]       = C1[i];
        pa[4096 + w * 512 + 256 + lane * 8 + i] = C1[8 + i];
    }
    __syncthreads();
#pragma unroll
    for (int bb = 0; bb < 2; bb++) {
        int b = bb ? b1 : b0;
        int mhB = b >> 7, rowB = b & 127;
        const float* pm = pms + bb * 16;
        const float* pp = pa + bb * 4096;
        float Mg = -1e30f;
#pragma unroll
        for (int ww = 0; ww < 8; ww++) Mg = fmaxf(Mg, pm[ww * 2]);
        float Sg = 0.f;
        float scl[8];
#pragma unroll
        for (int ww = 0; ww < 8; ww++) {
            scl[ww] = __expf(pm[ww * 2] - Mg);
            Sg += pm[ww * 2 + 1] * scl[ww];
        }
        float inv = 1.f / Sg;
        for (int h = tid; h < HH; h += 256) {
            float a = 0.f;
#pragma unroll
            for (int ww = 0; ww < 8; ww++) a += pp[ww * 512 + h] * scl[ww];
            g_ctxc[(size_t)(mhB * 8 + (h >> 6)) * 8192 +
                   (size_t)(((h & 63) >> 3) * 128 + rowB) * 8 + (h & 7)] =
                __float2half(a * inv);
        }
    }
    __syncthreads();
}

__global__ void __launch_bounds__(256, 1) dec_persistent(
    const float* __restrict__ Wdi, const float* __restrict__ Wdh,
    const float* __restrict__ bdi, const float* __restrict__ bdh,
    const float* __restrict__ Wfc, const float* __restrict__ bfc,
    float* __restrict__ out) {
    extern __shared__ __align__(16) char smc[];
    __half* Wsm = (__half*)smc;
    float* pa  = (float*)(smc + DOF_PA);
    float* pms = (float*)(smc + DOF_PMS);
    float* bqd = (float*)(smc + DOF_BQ);
    float* wd0 = (float*)(smc + DOF_WD0);
    uint32_t smb = smem_u32(smc);

    int bx = blockIdx.x, tid = threadIdx.x;
    int lane = tid & 31, wid = tid >> 5;
    int wm = wid >> 1, wn = wid & 1;
    int i4 = lane >> 3, r8 = lane & 7;
    int er = lane >> 2, ec = lane & 3;
    int mh = bx & 1;
    int nb8 = (bx >> 1) * 8;
    int ab0 = mh * 128 + (bx >> 1);
    int ab1 = ab0 + 64;

    for (int idx = tid; idx < 32 * 256; idx += 256) {
        int cc = idx >> 8, k4 = (idx & 255) * 4;
        int gate = (cc & 1) | (((cc >> 3) & 1) << 1);
        int n = nb8 + ((cc >> 4) & 1) * 4 + ((cc >> 1) & 3);
        int row = gate * HH + n;
        float w4[4];
        if (k4 < HH) {
            const float* sp = Wdi + (size_t)row * (HH + 1) + 1 + k4;
            w4[0] = sp[0]; w4[1] = sp[1]; w4[2] = sp[2]; w4[3] = sp[3];
        } else {
            float4 wv = *(const float4*)(Wdh + (size_t)row * HH + (k4 - HH));
            w4[0] = wv.x; w4[1] = wv.y; w4[2] = wv.z; w4[3] = wv.w;
        }
        __half* d = Wsm + (size_t)cc * 1032 + k4;
        d[0] = __float2half(w4[0]); d[1] = __float2half(w4[1]);
        d[2] = __float2half(w4[2]); d[3] = __float2half(w4[3]);
    }
    if (tid < 32) {
        int nl = tid >> 2, g = tid & 3;
        int row = g * HH + nb8 + nl;
        bqd[nl * 4 + g] = bdi[row] + bdh[row];
        wd0[nl * 4 + g] = Wdi[(size_t)row * (HH + 1)];
    }
    if (tid == 0) {
#pragma unroll
        for (int p = 0; p < 4; p++) mbar_init(smb + DOF_MBAR + p * 8, 1);
    }
    __syncthreads();

    uint32_t albase = ((uint32_t)((i4 >> 1) & 1)) * 2048 +
                      (uint32_t)(wm * 32 + (i4 & 1) * 8 + r8) * 16;
    int bcol = wn * 16 + ((i4 >> 1) & 1) * 8 + r8;
    int bkh = (i4 & 1) * 8;

    float cst[4];
#pragma unroll
    for (int mi = 0; mi < 2; mi++)
#pragma unroll
        for (int rh = 0; rh < 2; rh++) {
            int b = mh * 128 + wm * 32 + mi * 16 + rh * 8 + er;
            cst[mi * 2 + rh] = g_c1f[(size_t)b * HH + nb8 + wn * 4 + ec];
        }

    unsigned cF[4] = {0, 0, 0, 0};
    unsigned round = 0;
    for (int ds = 0; ds <= PL; ds++) {
        const __half* p0 = g_ctxc + (size_t)mh * 8 * 8192;
        const __half* p1 = g_h1[ds & 1] + (size_t)mh * 8 * 8192;
        if (ds < PL && tid == 0) {
#pragma unroll
            for (int p = 0; p < 4; p++)
                issue_bulk(smb + DOF_AB + p * 16384, p1 + (size_t)p * 8192, 16384,
                           smb + DOF_MBAR + p * 8);
        }
        attn_two(ds, ab0, ab1, ds < PL, Wfc, bfc, out, pa, pms);
        if (ds == PL) break;

        float acc[2][2][4];
#pragma unroll
        for (int a = 0; a < 2; a++)
#pragma unroll
            for (int b = 0; b < 2; b++)
#pragma unroll
                for (int qd = 0; qd < 4; qd++) acc[a][b][qd] = 0.f;

        // Wdh * h1 half (gemm chunks 8..15) — before the ctx barrier
        dec_half(p1, 8, smb, acc, cF, albase, bcol, bkh, tid);
        gridbar(&g_bar_dec2[mh], round, 64);   // ctx ready, buffers free

        if (tid == 0) {
#pragma unroll
            for (int p = 0; p < 4; p++)
                issue_bulk(smb + DOF_AB + p * 16384, p0 + (size_t)p * 8192, 16384,
                           smb + DOF_MBAR + p * 8);
        }
        dec_half(p0, 0, smb, acc, cF, albase, bcol, bkh, tid);

        {
            int nl = wn * 4 + ec;
            int n = nb8 + nl;
            int kc = n >> 6;
            int seg = (n & 63) >> 3;
            __half* hb = g_h1[(ds + 1) & 1];
#pragma unroll
            for (int mi = 0; mi < 2; mi++)
#pragma unroll
                for (int rh = 0; rh < 2; rh++) {
                    int row = wm * 32 + mi * 16 + rh * 8 + er;
                    int b = mh * 128 + row;
                    float y = g_yprev[b];
                    const float* bp = bqd + nl * 4;
                    const float* wp = wd0 + nl * 4;
                    float g0 = acc[mi][0][rh * 2]     + bp[0] + wp[0] * y;
                    float g1 = acc[mi][0][rh * 2 + 1] + bp[1] + wp[1] * y;
                    float g2 = acc[mi][1][rh * 2]     + bp[2] + wp[2] * y;
                    float g3 = acc[mi][1][rh * 2 + 1] + bp[3] + wp[3] * y;
                    float ig = sigf(g0), fg = sigf(g1);
                    float gg = tanhf(g2), og = sigf(g3);
                    float cv = fg * cst[mi * 2 + rh] + ig * gg;
                    cst[mi * 2 + rh] = cv;
                    hb[(size_t)(mh * 8 + kc) * 8192 + (size_t)(seg * 128 + row) * 8 +
                       (n & 7)] = __float2half(og * tanhf(cv));
                }
        }
        gridbar(&g_bar_dec2[mh], round, 64);
    }
}

extern "C" void kernel_launch(void* const* d_in, const int* in_sizes, int n_in,
                              void* d_out, int out_size) {
    const float* x    = (const float*)d_in[0];
    const float* Wih0 = (const float*)d_in[1];
    const float* Whh0 = (const float*)d_in[2];
    const float* bi0  = (const float*)d_in[3];
    const float* bh0  = (const float*)d_in[4];
    const float* Wih1 = (const float*)d_in[5];
    const float* Whh1 = (const float*)d_in[6];
    const float* bi1  = (const float*)d_in[7];
    const float* bh1  = (const float*)d_in[8];
    const float* Wdi  = (const float*)d_in[9];
    const float* Wdh  = (const float*)d_in[10];
    const float* bdi  = (const float*)d_in[11];
    const float* bdh  = (const float*)d_in[12];
    const float* Wfc  = (const float*)d_in[13];
    const float* bfc  = (const float*)d_in[14];
    float* out = (float*)d_out;

    cudaFuncSetAttribute(enc_persistent, cudaFuncAttributeMaxDynamicSharedMemorySize, ENC_SMEM);
    cudaFuncSetAttribute(dec_persistent, cudaFuncAttributeMaxDynamicSharedMemorySize, DEC_SMEM);

    prep_kernel<<<(BB * HH + 255) / 256, 256>>>();
    xp_kernel<<<dim3(LL, 128), 256>>>(x, Wih0, bi0, bh0);
    enc_persistent<<<NBE, 256, ENC_SMEM>>>(Whh0, Wih1, Whh1, bi1, bh1);
    dec_persistent<<<NBD, 256, DEC_SMEM>>>(Wdi, Wdh, bdi, bdh, Wfc, bfc, out);
}